// round 7
// baseline (speedup 1.0000x reference)
#include <cuda_runtime.h>
#include <stdint.h>
#include <math.h>

#define MAXB 64
#define TPB 256
#define NCTA 1480

struct Meta {
    unsigned prefix[MAXB + 1];    // element offset of piece i in output
    unsigned rowPrefix[MAXB + 1]; // row offset of piece i (H*s_i rows per batch)
    unsigned s[MAXB];
    unsigned s2[MAXB];
    unsigned ms[MAXB];            // magic for divide-by-s
    unsigned shs[MAXB];
    unsigned totalRows;
};

__device__ Meta g_meta;

// Granlund-Montgomery round-up magic: q = (x*m) >> sh == x/d for x < 2^31, d >= 2.
__device__ __forceinline__ void magic_u32(unsigned d, unsigned& m, unsigned& sh) {
    unsigned k = 32u - __clz(d - 1u);
    unsigned long long two = 1ull << (31 + k);
    m = (unsigned)((two + d - 1ull) / d);
    sh = 31u + k;
}

__global__ void setup_kernel(const int* __restrict__ seq, const int* __restrict__ nh, int B) {
    if (threadIdx.x != 0 || blockIdx.x != 0) return;
    unsigned H = nh ? (unsigned)(*nh) : 16u;
    unsigned acc = 0, racc = 0;
    for (int i = 0; i < B; ++i) {
        unsigned s = (unsigned)seq[i];
        unsigned s2 = s * s;
        g_meta.prefix[i] = acc;
        g_meta.rowPrefix[i] = racc;
        g_meta.s[i] = s;
        g_meta.s2[i] = s2;
        magic_u32(s, g_meta.ms[i], g_meta.shs[i]);
        acc += H * s2;
        racc += H * s;
    }
    g_meta.prefix[B] = acc;
    g_meta.rowPrefix[B] = racc;
    g_meta.totalRows = racc;
}

// Persistent CTAs grid-striding over the exact list of output rows.
// Each row is a contiguous copy: src row is 16B-aligned; dst run has
// block-uniform misalignment handled via window loads.
__global__ void __launch_bounds__(TPB)
copy_rows_kernel(const float* __restrict__ mask, float* __restrict__ out,
                 unsigned out_size, unsigned S, int B) {
    __shared__ unsigned sh_prefix[MAXB + 1], sh_rowPrefix[MAXB + 1];
    __shared__ unsigned sh_s[MAXB], sh_s2[MAXB], sh_ms[MAXB], sh_shs[MAXB];
    __shared__ unsigned sh_totalRows;

    for (int t = threadIdx.x; t <= B; t += TPB) {
        sh_prefix[t] = g_meta.prefix[t];
        sh_rowPrefix[t] = g_meta.rowPrefix[t];
    }
    for (int t = threadIdx.x; t < B; t += TPB) {
        sh_s[t] = g_meta.s[t];   sh_s2[t] = g_meta.s2[t];
        sh_ms[t] = g_meta.ms[t]; sh_shs[t] = g_meta.shs[t];
    }
    if (threadIdx.x == 0) sh_totalRows = g_meta.totalRows;
    __syncthreads();

    const unsigned t = threadIdx.x;
    const unsigned totalRows = sh_totalRows;

    for (unsigned w = blockIdx.x; w < totalRows; w += gridDim.x) {
        // decode w -> (batch i, head h, row r); all CTA-uniform
        int i = 0;
        while (i + 1 < B && w >= sh_rowPrefix[i + 1]) ++i;
        unsigned rem = w - sh_rowPrefix[i];
        unsigned s   = sh_s[i];
        unsigned h   = (unsigned)(((unsigned long long)rem * sh_ms[i]) >> sh_shs[i]);
        unsigned r   = rem - h * s;

        unsigned off = sh_prefix[i] + h * sh_s2[i] + r * s;
        unsigned len = s;
        if (off >= out_size) continue;
        if (len > out_size - off) len = out_size - off;

        const float* __restrict__ src = mask + ((size_t)i * S + r) * (size_t)S;
        float*       __restrict__ dst = out + off;

        unsigned lead = (4u - (off & 3u)) & 3u;  // bring dst to 16B alignment
        if (lead > len) lead = len;
        if (t < lead) dst[t] = src[t];           // scalar head

        const unsigned n  = len - lead;
        const unsigned n4 = n >> 2;
        float* vdst = dst + lead;
        const unsigned b = lead;                 // source misalign (0..3)

        if (b == 0u) {
            const float4* vsrc = reinterpret_cast<const float4*>(src);
            float4*       vd   = reinterpret_cast<float4*>(vdst);
            for (unsigned k = t; k < n4; k += TPB)
                vd[k] = vsrc[k];                 // LDG.128 + STG.128
        } else {
            // window base = src (row-aligned); overread <= 3 floats past len
            // stays inside the row since s <= S-1.
            const float4* wsrc = reinterpret_cast<const float4*>(src);
            float4*       vd   = reinterpret_cast<float4*>(vdst);
            for (unsigned k = t; k < n4; k += TPB) {
                float4 W0 = wsrc[k];
                float4 W1 = wsrc[k + 1u];
                float4 R;
                R.x = (b == 1u) ? W0.y : (b == 2u) ? W0.z : W0.w;
                R.y = (b == 1u) ? W0.z : (b == 2u) ? W0.w : W1.x;
                R.z = (b == 1u) ? W0.w : (b == 2u) ? W1.x : W1.y;
                R.w = (b == 1u) ? W1.x : (b == 2u) ? W1.y : W1.z;
                vd[k] = R;
            }
        }

        const unsigned done = lead + (n4 << 2);  // scalar tail (< 4 elems)
        const unsigned rtl  = len - done;
        if (t < rtl) dst[done + t] = src[done + t];
    }
}

extern "C" void kernel_launch(void* const* d_in, const int* in_sizes, int n_in,
                              void* d_out, int out_size) {
    const float* mask = (const float*)d_in[0];
    const int* seq = (const int*)d_in[1];
    const int* nh = (n_in >= 3) ? (const int*)d_in[2] : nullptr;

    int B = in_sizes[1];
    if (B > MAXB) B = MAXB;
    long long SS = (long long)in_sizes[0] / (B > 0 ? B : 1);
    unsigned S = (unsigned)(sqrt((double)SS) + 0.5);

    setup_kernel<<<1, 32>>>(seq, nh, B);

    if (out_size <= 0) return;
    copy_rows_kernel<<<NCTA, TPB>>>(mask, (float*)d_out, (unsigned)out_size, S, B);
}

// round 8
// speedup vs baseline: 1.5413x; 1.5413x over previous
#include <cuda_runtime.h>
#include <stdint.h>
#include <math.h>

#define MAXB 16
#define MAXH 32
#define MAXP (MAXB * (MAXH - 1))   // replicated pieces (h >= 1)
#define TPB 256
#define NCTA 1480
#define CHUNK_LOG 13u
#define CHUNK (1u << CHUNK_LOG)    // 8192 floats = 32KB per work unit

struct Meta {
    unsigned batchOff[MAXB + 1];   // output offset of batch i (head 0 piece)
    unsigned rowPrefix[MAXB + 1];  // prefix of s_i (phase-1 rows)
    unsigned s[MAXB];
    unsigned nP;                   // number of replicated pieces
    unsigned totalChunks;          // phase-2 work units
    unsigned totalRows0;           // phase-1 rows
    unsigned chunkPrefix[MAXP + 1];
    unsigned srcOff[MAXP];
    unsigned dstOff[MAXP];
    unsigned pieceLen[MAXP];
};
__device__ Meta g_meta;

__device__ __forceinline__ void st_cs(float4* p, float4 v) {
    asm volatile("st.global.cs.v4.f32 [%0], {%1,%2,%3,%4};"
                 :: "l"(p), "f"(v.x), "f"(v.y), "f"(v.z), "f"(v.w) : "memory");
}

__global__ void setup_kernel(const int* __restrict__ seq, const int* __restrict__ nh,
                             int B, unsigned out_size) {
    if (threadIdx.x != 0 || blockIdx.x != 0) return;
    unsigned H = nh ? (unsigned)(*nh) : 16u;
    if (H > MAXH) H = MAXH;
    unsigned acc = 0, racc = 0;
    for (int i = 0; i < B; ++i) {
        unsigned s = (unsigned)seq[i];
        g_meta.batchOff[i] = acc;
        g_meta.rowPrefix[i] = racc;
        g_meta.s[i] = s;
        acc += H * s * s;
        racc += s;
    }
    g_meta.batchOff[B] = acc;
    g_meta.rowPrefix[B] = racc;
    g_meta.totalRows0 = racc;

    unsigned p = 0, cacc = 0;
    for (int i = 0; i < B; ++i) {
        unsigned s = g_meta.s[i];
        unsigned s2 = s * s;
        for (unsigned h = 1; h < H && p < MAXP; ++h) {
            unsigned d = g_meta.batchOff[i] + h * s2;
            unsigned len = s2;
            if (d >= out_size) continue;
            if (len > out_size - d) len = out_size - d;
            g_meta.srcOff[p] = g_meta.batchOff[i];
            g_meta.dstOff[p] = d;
            g_meta.pieceLen[p] = len;
            g_meta.chunkPrefix[p] = cacc;
            cacc += (len + CHUNK - 1u) >> CHUNK_LOG;
            ++p;
        }
    }
    g_meta.nP = p;
    g_meta.chunkPrefix[p] = cacc;
    g_meta.totalChunks = cacc;
}

// ---- Phase 1: mask rows -> head-0 pieces (6% of bytes) ----
__global__ void __launch_bounds__(TPB)
phase1_rows(const float* __restrict__ mask, float* __restrict__ out,
            unsigned out_size, unsigned S, int B) {
    __shared__ unsigned sh_boff[MAXB + 1], sh_rp[MAXB + 1], sh_s[MAXB];
    __shared__ unsigned sh_rows;
    for (int t = threadIdx.x; t <= B; t += TPB) { sh_boff[t] = g_meta.batchOff[t]; sh_rp[t] = g_meta.rowPrefix[t]; }
    for (int t = threadIdx.x; t < B; t += TPB) sh_s[t] = g_meta.s[t];
    if (threadIdx.x == 0) sh_rows = g_meta.totalRows0;
    __syncthreads();

    const unsigned t = threadIdx.x;
    for (unsigned w = blockIdx.x; w < sh_rows; w += gridDim.x) {
        int i = 0;
        while (i + 1 < B && w >= sh_rp[i + 1]) ++i;
        unsigned r = w - sh_rp[i];
        unsigned s = sh_s[i];
        unsigned off = sh_boff[i] + r * s;
        unsigned len = s;
        if (off >= out_size) continue;
        if (len > out_size - off) len = out_size - off;

        const float* __restrict__ src = mask + ((size_t)i * S + r) * (size_t)S;
        float* __restrict__ dst = out + off;

        unsigned lead = (4u - (off & 3u)) & 3u;
        if (lead > len) lead = len;
        if (t < lead) dst[t] = src[t];

        unsigned n4 = (len - lead) >> 2;
        float4* vd = reinterpret_cast<float4*>(dst + lead);
        unsigned b = lead;
        if (b == 0u) {
            const float4* vs = reinterpret_cast<const float4*>(src);
            for (unsigned k = t; k < n4; k += TPB) vd[k] = vs[k];
        } else {
            // window base = src (row-aligned); overread <=3 floats stays in row (s <= S-1)
            const float4* ws = reinterpret_cast<const float4*>(src);
            for (unsigned k = t; k < n4; k += TPB) {
                float4 W0 = ws[k], W1 = ws[k + 1u], R;
                R.x = (b == 1u) ? W0.y : (b == 2u) ? W0.z : W0.w;
                R.y = (b == 1u) ? W0.z : (b == 2u) ? W0.w : W1.x;
                R.z = (b == 1u) ? W0.w : (b == 2u) ? W1.x : W1.y;
                R.w = (b == 1u) ? W1.x : (b == 2u) ? W1.y : W1.z;
                vd[k] = R;
            }
        }
        unsigned done = lead + (n4 << 2);
        if (t < len - done) dst[done + t] = src[done + t];
    }
}

// ---- Phase 2: replicate head-0 pieces to heads 1..H-1 (contiguous memcpy, 94%) ----
__global__ void __launch_bounds__(TPB)
phase2_replicate(float* __restrict__ out) {
    __shared__ unsigned scp[MAXP + 1], ssrc[MAXP], sdst[MAXP], slen[MAXP];
    __shared__ unsigned snP, stc;
    if (threadIdx.x == 0) { snP = g_meta.nP; stc = g_meta.totalChunks; }
    __syncthreads();
    const unsigned nP = snP;
    for (unsigned t = threadIdx.x; t <= nP; t += TPB) scp[t] = g_meta.chunkPrefix[t];
    for (unsigned t = threadIdx.x; t < nP; t += TPB) {
        ssrc[t] = g_meta.srcOff[t]; sdst[t] = g_meta.dstOff[t]; slen[t] = g_meta.pieceLen[t];
    }
    __syncthreads();

    const unsigned t = threadIdx.x;
    const unsigned total = stc;

    for (unsigned u = blockIdx.x; u < total; u += gridDim.x) {
        // binary search piece: scp[p] <= u < scp[p+1]
        unsigned lo = 0, hi = nP - 1u;
        while (lo < hi) {
            unsigned mid = (lo + hi + 1u) >> 1;
            if (u >= scp[mid]) lo = mid; else hi = mid - 1u;
        }
        const unsigned p = lo;
        unsigned rel = (u - scp[p]) << CHUNK_LOG;
        unsigned len = slen[p] - rel;
        if (len > CHUNK) len = CHUNK;
        const unsigned dst0 = sdst[p] + rel;
        const unsigned src0 = ssrc[p] + rel;

        unsigned hc = (4u - (dst0 & 3u)) & 3u;   // bring dst to 16B alignment
        if (hc > len) hc = len;
        if (t < hc) out[dst0 + t] = out[src0 + t];

        const unsigned n4 = (len - hc) >> 2;
        float4* vd = reinterpret_cast<float4*>(out + dst0 + hc);
        const unsigned sbase = src0 + hc;
        const unsigned b = sbase & 3u;

        if (b == 0u) {
            const float4* vs = reinterpret_cast<const float4*>(out + sbase);
            unsigned k = t;
            for (; k + 3u * TPB < n4; k += 4u * TPB) {
                float4 a0 = vs[k], a1 = vs[k + TPB], a2 = vs[k + 2u * TPB], a3 = vs[k + 3u * TPB];
                st_cs(vd + k, a0);
                st_cs(vd + k + TPB, a1);
                st_cs(vd + k + 2u * TPB, a2);
                st_cs(vd + k + 3u * TPB, a3);
            }
            for (; k < n4; k += TPB) { float4 a = vs[k]; st_cs(vd + k, a); }
        } else {
            // window loads from aligned base; overread lands in the next piece
            // (>= s^2 >= 16384 floats of slack after any head-0 piece); overread
            // lanes are discarded by the SELs below.
            const float4* ws = reinterpret_cast<const float4*>(out + (sbase & ~3u));
            unsigned k = t;
            for (; k + 3u * TPB < n4; k += 4u * TPB) {
                float4 W0a = ws[k],            W1a = ws[k + 1u];
                float4 W0b = ws[k + TPB],      W1b = ws[k + TPB + 1u];
                float4 W0c = ws[k + 2u * TPB], W1c = ws[k + 2u * TPB + 1u];
                float4 W0d = ws[k + 3u * TPB], W1d = ws[k + 3u * TPB + 1u];
                float4 R;
                R.x = (b == 1u) ? W0a.y : (b == 2u) ? W0a.z : W0a.w;
                R.y = (b == 1u) ? W0a.z : (b == 2u) ? W0a.w : W1a.x;
                R.z = (b == 1u) ? W0a.w : (b == 2u) ? W1a.x : W1a.y;
                R.w = (b == 1u) ? W1a.x : (b == 2u) ? W1a.y : W1a.z;
                st_cs(vd + k, R);
                R.x = (b == 1u) ? W0b.y : (b == 2u) ? W0b.z : W0b.w;
                R.y = (b == 1u) ? W0b.z : (b == 2u) ? W0b.w : W1b.x;
                R.z = (b == 1u) ? W0b.w : (b == 2u) ? W1b.x : W1b.y;
                R.w = (b == 1u) ? W1b.x : (b == 2u) ? W1b.y : W1b.z;
                st_cs(vd + k + TPB, R);
                R.x = (b == 1u) ? W0c.y : (b == 2u) ? W0c.z : W0c.w;
                R.y = (b == 1u) ? W0c.z : (b == 2u) ? W0c.w : W1c.x;
                R.z = (b == 1u) ? W0c.w : (b == 2u) ? W1c.x : W1c.y;
                R.w = (b == 1u) ? W1c.x : (b == 2u) ? W1c.y : W1c.z;
                st_cs(vd + k + 2u * TPB, R);
                R.x = (b == 1u) ? W0d.y : (b == 2u) ? W0d.z : W0d.w;
                R.y = (b == 1u) ? W0d.z : (b == 2u) ? W0d.w : W1d.x;
                R.z = (b == 1u) ? W0d.w : (b == 2u) ? W1d.x : W1d.y;
                R.w = (b == 1u) ? W1d.x : (b == 2u) ? W1d.y : W1d.z;
                st_cs(vd + k + 3u * TPB, R);
            }
            for (; k < n4; k += TPB) {
                float4 W0 = ws[k], W1 = ws[k + 1u], R;
                R.x = (b == 1u) ? W0.y : (b == 2u) ? W0.z : W0.w;
                R.y = (b == 1u) ? W0.z : (b == 2u) ? W0.w : W1.x;
                R.z = (b == 1u) ? W0.w : (b == 2u) ? W1.x : W1.y;
                R.w = (b == 1u) ? W1.x : (b == 2u) ? W1.y : W1.z;
                st_cs(vd + k, R);
            }
        }

        const unsigned done = hc + (n4 << 2);
        if (t < len - done) out[dst0 + done + t] = out[src0 + done + t];
    }
}

extern "C" void kernel_launch(void* const* d_in, const int* in_sizes, int n_in,
                              void* d_out, int out_size) {
    const float* mask = (const float*)d_in[0];
    const int* seq = (const int*)d_in[1];
    const int* nh = (n_in >= 3) ? (const int*)d_in[2] : nullptr;

    int B = in_sizes[1];
    if (B > MAXB) B = MAXB;
    long long SS = (long long)in_sizes[0] / (B > 0 ? B : 1);
    unsigned S = (unsigned)(sqrt((double)SS) + 0.5);

    if (out_size <= 0) return;
    setup_kernel<<<1, 32>>>(seq, nh, B, (unsigned)out_size);
    phase1_rows<<<NCTA, TPB>>>(mask, (float*)d_out, (unsigned)out_size, S, B);
    phase2_replicate<<<NCTA, TPB>>>((float*)d_out);
}

// round 9
// speedup vs baseline: 1.8781x; 1.2185x over previous
#include <cuda_runtime.h>
#include <stdint.h>
#include <math.h>

#define MAXB 16
#define MAXH 32
#define TPB 256
#define NCTA 1480
#define SBUF_N 2056   // max row (2047) + 4 window slack, padded

__device__ __forceinline__ void st_cs(float4* p, float4 v) {
    asm volatile("st.global.cs.v4.f32 [%0], {%1,%2,%3,%4};"
                 :: "l"(p), "f"(v.x), "f"(v.y), "f"(v.z), "f"(v.w) : "memory");
}

// Single fused persistent kernel:
//  - per-CTA meta build (parallel seq loads, tiny prefix loop)
//  - CTA per source row: stage row in SMEM once, fan out to all H heads.
__global__ void __launch_bounds__(TPB)
fused_kernel(const float* __restrict__ mask, const int* __restrict__ seq,
             const int* __restrict__ nh, float* __restrict__ out,
             unsigned out_size, unsigned S, int B) {
    __shared__ unsigned sh_s[MAXB];
    __shared__ unsigned sh_boff[MAXB + 1];   // output offset of batch i
    __shared__ unsigned sh_rp[MAXB + 1];     // prefix of s_i (row ids)
    __shared__ unsigned sh_H, sh_rows;
    __shared__ __align__(16) float sbuf[SBUF_N];

    const unsigned t = threadIdx.x;

    if (t < (unsigned)B) sh_s[t] = (unsigned)seq[t];
    if (t == 0) {
        unsigned H = nh ? (unsigned)(*nh) : 16u;
        if (H > MAXH) H = MAXH;
        sh_H = H;
    }
    __syncthreads();
    if (t == 0) {
        unsigned acc = 0, racc = 0, H = sh_H;
        for (int i = 0; i < B; ++i) {
            unsigned s = sh_s[i];
            sh_boff[i] = acc;
            sh_rp[i] = racc;
            acc += H * s * s;
            racc += s;
        }
        sh_boff[B] = acc;
        sh_rp[B] = racc;
        sh_rows = racc;
    }
    __syncthreads();

    const unsigned H = sh_H;
    const unsigned totalRows = sh_rows;

    for (unsigned w = blockIdx.x; w < totalRows; w += gridDim.x) {
        // decode row id -> (batch i, row r); CTA-uniform
        int i = 0;
        while (i + 1 < B && w >= sh_rp[i + 1]) ++i;
        const unsigned r = w - sh_rp[i];
        const unsigned s = sh_s[i];
        const unsigned s2 = s * s;
        const unsigned boff = sh_boff[i];

        // ---- stage source row (+4 floats window slack) into SMEM ----
        // row base is 16B-aligned (multiple of S); overread of <=1 extra
        // float4 stays inside the mask allocation since r <= S-2.
        {
            const float4* src4 = reinterpret_cast<const float4*>(
                mask + ((size_t)i * S + r) * (size_t)S);
            float4* sb4 = reinterpret_cast<float4*>(sbuf);
            const unsigned nld = (s + 7u) >> 2;   // covers s+4 floats
            for (unsigned k = t; k < nld; k += TPB) sb4[k] = src4[k];
        }
        __syncthreads();

        // ---- fan out to all H head destinations ----
        for (unsigned h = 0; h < H; ++h) {
            unsigned off = boff + h * s2 + r * s;
            if (off >= out_size) continue;
            unsigned len = s;
            if (len > out_size - off) len = out_size - off;

            unsigned lead = (4u - (off & 3u)) & 3u;   // align dst to 16B
            if (lead > len) lead = len;
            if (t < lead) out[off + t] = sbuf[t];     // scalar head

            const unsigned n4 = (len - lead) >> 2;
            float4* vd = reinterpret_cast<float4*>(out + off + lead);
            const unsigned b = lead;                  // smem read shift 0..3
            const float4* sb4 = reinterpret_cast<const float4*>(sbuf);

            if (b == 0u) {
                for (unsigned k = t; k < n4; k += TPB)
                    st_cs(vd + k, sb4[k]);            // LDS.128 + STG.128
            } else {
                // conflict-free LDS.128 window + uniform SELs; reads up to
                // sbuf[4*n4+7] <= sbuf[s+3] < SBUF_N, garbage lanes discarded.
                for (unsigned k = t; k < n4; k += TPB) {
                    float4 W0 = sb4[k];
                    float4 W1 = sb4[k + 1u];
                    float4 R;
                    R.x = (b == 1u) ? W0.y : (b == 2u) ? W0.z : W0.w;
                    R.y = (b == 1u) ? W0.z : (b == 2u) ? W0.w : W1.x;
                    R.z = (b == 1u) ? W0.w : (b == 2u) ? W1.x : W1.y;
                    R.w = (b == 1u) ? W1.x : (b == 2u) ? W1.y : W1.z;
                    st_cs(vd + k, R);
                }
            }

            const unsigned done = lead + (n4 << 2);   // scalar tail (<4)
            if (t < len - done) out[off + done + t] = sbuf[done + t];
        }
        __syncthreads();   // before next row overwrites sbuf
    }
}

extern "C" void kernel_launch(void* const* d_in, const int* in_sizes, int n_in,
                              void* d_out, int out_size) {
    const float* mask = (const float*)d_in[0];
    const int* seq = (const int*)d_in[1];
    const int* nh = (n_in >= 3) ? (const int*)d_in[2] : nullptr;

    int B = in_sizes[1];
    if (B > MAXB) B = MAXB;
    long long SS = (long long)in_sizes[0] / (B > 0 ? B : 1);
    unsigned S = (unsigned)(sqrt((double)SS) + 0.5);

    if (out_size <= 0) return;
    fused_kernel<<<NCTA, TPB>>>(mask, seq, nh, (float*)d_out,
                                (unsigned)out_size, S, B);
}

// round 10
// speedup vs baseline: 1.9026x; 1.0131x over previous
#include <cuda_runtime.h>
#include <stdint.h>
#include <math.h>

#define MAXB 16
#define MAXH 32
#define TPB 256
#define NWARP (TPB / 32)
#define NCTA 1480
#define SBUF_N 2056   // max row (2047) + window slack, 16B-multiple

__device__ __forceinline__ void st_cs(float4* p, float4 v) {
    asm volatile("st.global.cs.v4.f32 [%0], {%1,%2,%3,%4};"
                 :: "l"(p), "f"(v.x), "f"(v.y), "f"(v.z), "f"(v.w) : "memory");
}

// Fused persistent kernel. CTA per source row:
//   1) stage row in SMEM (block-wide, aligned LDG.128)
//   2) warp-per-head fan-out: each warp owns whole head copies, so all
//      per-head fixed cost (offset math, head/tail, loop prologue) is paid
//      by one warp instead of eight.
__global__ void __launch_bounds__(TPB)
fused_kernel(const float* __restrict__ mask, const int* __restrict__ seq,
             const int* __restrict__ nh, float* __restrict__ out,
             unsigned out_size, unsigned S, int B) {
    __shared__ unsigned sh_s[MAXB];
    __shared__ unsigned sh_boff[MAXB + 1];
    __shared__ unsigned sh_rp[MAXB + 1];
    __shared__ unsigned sh_H, sh_rows;
    __shared__ __align__(16) float sbuf[SBUF_N];

    const unsigned t = threadIdx.x;
    const unsigned lane = t & 31u;
    const unsigned wid  = t >> 5;

    if (t < (unsigned)B) sh_s[t] = (unsigned)seq[t];
    if (t == 0) {
        unsigned H = nh ? (unsigned)(*nh) : 16u;
        if (H > MAXH) H = MAXH;
        if (H < 1u) H = 1u;
        sh_H = H;
    }
    __syncthreads();
    if (t == 0) {
        unsigned acc = 0, racc = 0, H = sh_H;
        for (int i = 0; i < B; ++i) {
            unsigned s = sh_s[i];
            sh_boff[i] = acc;
            sh_rp[i] = racc;
            acc += H * s * s;
            racc += s;
        }
        sh_boff[B] = acc;
        sh_rp[B] = racc;
        sh_rows = racc;
    }
    __syncthreads();

    const unsigned H = sh_H;
    const unsigned totalRows = sh_rows;

    for (unsigned w = blockIdx.x; w < totalRows; w += gridDim.x) {
        // decode row id -> (batch i, row r); CTA-uniform
        int i = 0;
        while (i + 1 < B && w >= sh_rp[i + 1]) ++i;
        const unsigned r = w - sh_rp[i];
        const unsigned s = sh_s[i];
        const unsigned s2 = s * s;
        const unsigned boff = sh_boff[i];

        // ---- stage source row (+slack) in SMEM; row base is 16B-aligned;
        //      overread stays inside mask since r <= S-2. ----
        {
            const float4* src4 = reinterpret_cast<const float4*>(
                mask + ((size_t)i * S + r) * (size_t)S);
            float4* sb4 = reinterpret_cast<float4*>(sbuf);
            const unsigned nld = (s + 7u) >> 2;
            for (unsigned k = t; k < nld; k += TPB) sb4[k] = src4[k];
        }
        __syncthreads();

        // ---- warp-per-head fan-out ----
        for (unsigned h = wid; h < H; h += NWARP) {
            unsigned off = boff + h * s2 + r * s;
            if (off >= out_size) continue;
            unsigned len = s;
            if (len > out_size - off) len = out_size - off;

            unsigned lead = (4u - (off & 3u)) & 3u;   // align dst to 16B
            if (lead > len) lead = len;
            if (lane < lead) out[off + lane] = sbuf[lane];

            const unsigned n4 = (len - lead) >> 2;
            float4* vd = reinterpret_cast<float4*>(out + off + lead);
            const unsigned b = lead;                  // smem base shift 0..3

            if (b == 0u) {
                const float4* sp = reinterpret_cast<const float4*>(sbuf);
                for (unsigned k = lane; k < n4; k += 32u)
                    st_cs(vd + k, sp[k]);             // LDS.128 + STG.128
            } else if (b == 2u) {
                // 8B-aligned smem base: two LDS.64 per float4, no SELs
                const float2* sp = reinterpret_cast<const float2*>(sbuf + 2u);
                for (unsigned k = lane; k < n4; k += 32u) {
                    float2 u = sp[2u * k];
                    float2 v = sp[2u * k + 1u];
                    float4 R; R.x = u.x; R.y = u.y; R.z = v.x; R.w = v.y;
                    st_cs(vd + k, R);
                }
            } else {
                // 4B-aligned: four LDS.32 per float4, no SELs
                const float* sp = sbuf + b;
                for (unsigned k = lane; k < n4; k += 32u) {
                    unsigned e = 4u * k;
                    float4 R;
                    R.x = sp[e]; R.y = sp[e + 1u]; R.z = sp[e + 2u]; R.w = sp[e + 3u];
                    st_cs(vd + k, R);
                }
            }

            const unsigned done = lead + (n4 << 2);   // scalar tail (<4)
            if (lane < len - done) out[off + done + lane] = sbuf[done + lane];
        }
        __syncthreads();   // before next row overwrites sbuf
    }
}

extern "C" void kernel_launch(void* const* d_in, const int* in_sizes, int n_in,
                              void* d_out, int out_size) {
    const float* mask = (const float*)d_in[0];
    const int* seq = (const int*)d_in[1];
    const int* nh = (n_in >= 3) ? (const int*)d_in[2] : nullptr;

    int B = in_sizes[1];
    if (B > MAXB) B = MAXB;
    long long SS = (long long)in_sizes[0] / (B > 0 ? B : 1);
    unsigned S = (unsigned)(sqrt((double)SS) + 0.5);

    if (out_size <= 0) return;
    fused_kernel<<<NCTA, TPB>>>(mask, seq, nh, (float*)d_out,
                                (unsigned)out_size, S, B);
}

// round 11
// speedup vs baseline: 1.9740x; 1.0375x over previous
#include <cuda_runtime.h>
#include <stdint.h>
#include <math.h>

#define MAXB 16
#define MAXH 32
#define TPB 256
#define NWARP (TPB / 32)
#define NCTA 1480
#define SBUF_N 2064   // max row (2047) + window slack, 16B-multiple

__device__ __forceinline__ void st_cs(float4* p, float4 v) {
    asm volatile("st.global.cs.v4.f32 [%0], {%1,%2,%3,%4};"
                 :: "l"(p), "f"(v.x), "f"(v.y), "f"(v.z), "f"(v.w) : "memory");
}
__device__ __forceinline__ void cp_async16(unsigned saddr, const void* gptr) {
    asm volatile("cp.async.ca.shared.global [%0], [%1], 16;"
                 :: "r"(saddr), "l"(gptr));
}
#define CP_COMMIT() asm volatile("cp.async.commit_group;" ::: "memory")
#define CP_WAIT(n)  asm volatile("cp.async.wait_group %0;" :: "n"(n) : "memory")

// Fused persistent kernel, double-buffered:
//   stage(row n+1) via cp.async overlaps fan-out(row n) from SMEM.
//   Fan-out: warp-per-head so per-head fixed cost is paid once.
__global__ void __launch_bounds__(TPB)
fused_kernel(const float* __restrict__ mask, const int* __restrict__ seq,
             const int* __restrict__ nh, float* __restrict__ out,
             unsigned out_size, unsigned S, int B) {
    __shared__ unsigned sh_s[MAXB];
    __shared__ unsigned sh_boff[MAXB + 1];
    __shared__ unsigned sh_rp[MAXB + 1];
    __shared__ unsigned sh_H, sh_rows;
    __shared__ __align__(16) float sbuf[2][SBUF_N];

    const unsigned t = threadIdx.x;
    const unsigned lane = t & 31u;
    const unsigned wid  = t >> 5;

    if (t < (unsigned)B) sh_s[t] = (unsigned)seq[t];
    if (t == 0) {
        unsigned H = nh ? (unsigned)(*nh) : 16u;
        if (H > MAXH) H = MAXH;
        if (H < 1u) H = 1u;
        sh_H = H;
    }
    __syncthreads();
    if (t == 0) {
        unsigned acc = 0, racc = 0, H = sh_H;
        for (int i = 0; i < B; ++i) {
            unsigned s = sh_s[i];
            sh_boff[i] = acc;
            sh_rp[i] = racc;
            acc += H * s * s;
            racc += s;
        }
        sh_boff[B] = acc;
        sh_rp[B] = racc;
        sh_rows = racc;
    }
    __syncthreads();

    const unsigned H = sh_H;
    const unsigned totalRows = sh_rows;

    // decode helper values for a row id (CTA-uniform, cheap: B <= 16)
    auto decode = [&](unsigned w, unsigned& i, unsigned& r, unsigned& s) {
        unsigned ii = 0;
        while (ii + 1u < (unsigned)B && w >= sh_rp[ii + 1u]) ++ii;
        i = ii; r = w - sh_rp[ii]; s = sh_s[ii];
    };
    // issue cp.async staging of row (i,r) into buffer buf (no wait)
    auto stage = [&](unsigned buf, unsigned i, unsigned r, unsigned s) {
        const float4* src4 = reinterpret_cast<const float4*>(
            mask + ((size_t)i * S + r) * (size_t)S);
        unsigned sb = (unsigned)__cvta_generic_to_shared(&sbuf[buf][0]);
        const unsigned nld = (s + 7u) >> 2;   // covers s+4 floats of window slack
        for (unsigned k = t; k < nld; k += TPB)
            cp_async16(sb + 16u * k, src4 + k);
    };

    unsigned w = blockIdx.x;
    if (w >= totalRows) return;

    unsigned ci, cr, cs;
    decode(w, ci, cr, cs);
    stage(0, ci, cr, cs);
    CP_COMMIT();
    unsigned cur = 0;

    for (; w < totalRows; w += gridDim.x) {
        const unsigned wn = w + gridDim.x;
        const bool havenext = (wn < totalRows);
        unsigned ni = 0, nr = 0, ns = 0;
        if (havenext) {
            decode(wn, ni, nr, ns);
            stage(cur ^ 1u, ni, nr, ns);      // overlap with fan-out below
            CP_COMMIT();
            CP_WAIT(1);                        // current buffer complete
        } else {
            CP_WAIT(0);
        }
        __syncthreads();                       // staged data visible to all warps

        const unsigned s2 = cs * cs;
        const unsigned boff = sh_boff[ci];
        const float* sb = sbuf[cur];

        // ---- warp-per-head fan-out of row (ci, cr) ----
        for (unsigned h = wid; h < H; h += NWARP) {
            unsigned off = boff + h * s2 + cr * cs;
            if (off >= out_size) continue;
            unsigned len = cs;
            if (len > out_size - off) len = out_size - off;

            unsigned lead = (4u - (off & 3u)) & 3u;
            if (lead > len) lead = len;
            if (lane < lead) out[off + lane] = sb[lane];

            const unsigned n4 = (len - lead) >> 2;
            float4* vd = reinterpret_cast<float4*>(out + off + lead);
            const unsigned b = lead;

            if (b == 0u) {
                const float4* sp = reinterpret_cast<const float4*>(sb);
                for (unsigned k = lane; k < n4; k += 32u)
                    st_cs(vd + k, sp[k]);
            } else if (b == 2u) {
                const float2* sp = reinterpret_cast<const float2*>(sb + 2u);
                for (unsigned k = lane; k < n4; k += 32u) {
                    float2 u = sp[2u * k];
                    float2 v = sp[2u * k + 1u];
                    float4 R; R.x = u.x; R.y = u.y; R.z = v.x; R.w = v.y;
                    st_cs(vd + k, R);
                }
            } else {
                const float* sp = sb + b;
                for (unsigned k = lane; k < n4; k += 32u) {
                    unsigned e = 4u * k;
                    float4 R;
                    R.x = sp[e]; R.y = sp[e + 1u]; R.z = sp[e + 2u]; R.w = sp[e + 3u];
                    st_cs(vd + k, R);
                }
            }

            const unsigned done = lead + (n4 << 2);
            if (lane < len - done) out[off + done + lane] = sb[done + lane];
        }

        __syncthreads();    // all reads of cur done before it's restaged
        cur ^= 1u;
        ci = ni; cr = nr; cs = ns;
    }
}

extern "C" void kernel_launch(void* const* d_in, const int* in_sizes, int n_in,
                              void* d_out, int out_size) {
    const float* mask = (const float*)d_in[0];
    const int* seq = (const int*)d_in[1];
    const int* nh = (n_in >= 3) ? (const int*)d_in[2] : nullptr;

    int B = in_sizes[1];
    if (B > MAXB) B = MAXB;
    long long SS = (long long)in_sizes[0] / (B > 0 ? B : 1);
    unsigned S = (unsigned)(sqrt((double)SS) + 0.5);

    if (out_size <= 0) return;
    fused_kernel<<<NCTA, TPB>>>(mask, seq, nh, (float*)d_out,
                                (unsigned)out_size, S, B);
}